// round 1
// baseline (speedup 1.0000x reference)
#include <cuda_runtime.h>

// Problem constants
#define NB   32
#define NCH  3
#define HH   128
#define RR   127      // output spatial size = H - K + 1
#define NLOC (NB*RR*RR)

// Circuit matrix U (16x16, row-major): state' = U * s
__device__ float g_U[256];

// ---------------------------------------------------------------------------
// Prep: build U from weights by evolving the 16 basis columns through the
// circuit. Thread j owns column j (16 floats in registers).
// State index = (a<<3)|(b<<2)|(c<<1)|d, qubit q <-> bit (3-q).
// Per layer: RY(w[l][q]) on q=0..3, then CNOT(0,1), CNOT(2,3), CNOT(1,2).
// ---------------------------------------------------------------------------
__global__ void prep_kernel(const float* __restrict__ w) {
    int j = threadIdx.x;
    if (j >= 16) return;
    float m[16];
#pragma unroll
    for (int i = 0; i < 16; i++) m[i] = (i == j) ? 1.0f : 0.0f;

    for (int layer = 0; layer < 4; layer++) {
#pragma unroll
        for (int q = 0; q < 4; q++) {
            float t = 0.5f * w[layer * 4 + q];
            float c = cosf(t), s = sinf(t);
            int mask = 8 >> q;
#pragma unroll
            for (int i0 = 0; i0 < 16; i0++) {
                if (i0 & mask) continue;
                int i1 = i0 | mask;
                float a0 = m[i0], a1 = m[i1];
                m[i0] = c * a0 - s * a1;   // bit=0 slab
                m[i1] = s * a0 + c * a1;   // bit=1 slab
            }
        }
        // CNOT(ctrl,tgt): swap rows (i, i|tgt) for indices with ctrl set, tgt clear
        // CNOT(0,1): ctrl bit 8, tgt bit 4
#pragma unroll
        for (int i = 0; i < 16; i++)
            if ((i & 8) && !(i & 4)) { float tt = m[i]; m[i] = m[i | 4]; m[i | 4] = tt; }
        // CNOT(2,3): ctrl bit 2, tgt bit 1
#pragma unroll
        for (int i = 0; i < 16; i++)
            if ((i & 2) && !(i & 1)) { float tt = m[i]; m[i] = m[i | 1]; m[i | 1] = tt; }
        // CNOT(1,2): ctrl bit 4, tgt bit 2
#pragma unroll
        for (int i = 0; i < 16; i++)
            if ((i & 4) && !(i & 2)) { float tt = m[i]; m[i] = m[i | 2]; m[i | 2] = tt; }
    }
#pragma unroll
    for (int i = 0; i < 16; i++) g_U[i * 16 + j] = m[i];
}

// ---------------------------------------------------------------------------
// Main: one thread per output location (b,i,j).
//   s_c = product state from the 2x2 patch of channel c
//   P_r = sum_c (U_r . s_c)^2          (channel sum folded in: z linear in P)
//   z_q = signed butterfly over P      -> out[(b*R+i)*R+j]*4 + q
// ---------------------------------------------------------------------------
__global__ void __launch_bounds__(256) rqcnn_main(const float* __restrict__ x,
                                                  float* __restrict__ out) {
    __shared__ __align__(16) float sU[256];
    for (int k = threadIdx.x; k < 256; k += 256) sU[k] = g_U[k];
    __syncthreads();

    int gid = blockIdx.x * 256 + threadIdx.x;
    if (gid >= NLOC) return;

    int j = gid % RR;
    int t2 = gid / RR;
    int i = t2 % RR;
    int b = t2 / RR;

    const float HPI = 1.57079632679489662f;  // pi/2

    float s[NCH][16];
#pragma unroll
    for (int c = 0; c < NCH; c++) {
        const float* px = x + (((b * NCH + c) * HH) + i) * HH + j;
        float p00 = px[0], p01 = px[1], p10 = px[HH], p11 = px[HH + 1];
        float ca, sa, cb, sb, cc, sc, cd, sd;
        __sincosf(p00 * HPI, &sa, &ca);   // qubit 0 (a): pixel (i, j)
        __sincosf(p01 * HPI, &sb, &cb);   // qubit 1 (b): pixel (i, j+1)
        __sincosf(p10 * HPI, &sc, &cc);   // qubit 2 (c): pixel (i+1, j)
        __sincosf(p11 * HPI, &sd, &cd);   // qubit 3 (d): pixel (i+1, j+1)

        float ab00 = ca * cb, ab01 = ca * sb, ab10 = sa * cb, ab11 = sa * sb;
        float cd00 = cc * cd, cd01 = cc * sd, cd10 = sc * cd, cd11 = sc * sd;

        // s[(ia<<3)|(ib<<2)|(ic<<1)|id] = ab[ia][ib] * cd[ic][id]
        s[c][0]  = ab00 * cd00; s[c][1]  = ab00 * cd01; s[c][2]  = ab00 * cd10; s[c][3]  = ab00 * cd11;
        s[c][4]  = ab01 * cd00; s[c][5]  = ab01 * cd01; s[c][6]  = ab01 * cd10; s[c][7]  = ab01 * cd11;
        s[c][8]  = ab10 * cd00; s[c][9]  = ab10 * cd01; s[c][10] = ab10 * cd10; s[c][11] = ab10 * cd11;
        s[c][12] = ab11 * cd00; s[c][13] = ab11 * cd01; s[c][14] = ab11 * cd10; s[c][15] = ab11 * cd11;
    }

    float P[16];
#pragma unroll
    for (int r = 0; r < 16; r++) {
        const float4* row = reinterpret_cast<const float4*>(sU + r * 16);
        float4 u0 = row[0], u1 = row[1], u2 = row[2], u3 = row[3];
        float acc = 0.0f;
#pragma unroll
        for (int c = 0; c < NCH; c++) {
            float y;
            y = u0.x * s[c][0];
            y = fmaf(u0.y, s[c][1],  y);
            y = fmaf(u0.z, s[c][2],  y);
            y = fmaf(u0.w, s[c][3],  y);
            y = fmaf(u1.x, s[c][4],  y);
            y = fmaf(u1.y, s[c][5],  y);
            y = fmaf(u1.z, s[c][6],  y);
            y = fmaf(u1.w, s[c][7],  y);
            y = fmaf(u2.x, s[c][8],  y);
            y = fmaf(u2.y, s[c][9],  y);
            y = fmaf(u2.z, s[c][10], y);
            y = fmaf(u2.w, s[c][11], y);
            y = fmaf(u3.x, s[c][12], y);
            y = fmaf(u3.y, s[c][13], y);
            y = fmaf(u3.z, s[c][14], y);
            y = fmaf(u3.w, s[c][15], y);
            acc = fmaf(y, y, acc);
        }
        P[r] = acc;
    }

    // Signed reductions: z_q = sum_i sgn(bit_{3-q}(i)) * P_i
    float z3 = (P[0] - P[1]) + (P[2] - P[3]) + (P[4] - P[5]) + (P[6] - P[7])
             + (P[8] - P[9]) + (P[10] - P[11]) + (P[12] - P[13]) + (P[14] - P[15]);
    float e0 = P[0]  + P[1],  e1 = P[2]  + P[3],  e2 = P[4]  + P[5],  e3 = P[6]  + P[7];
    float e4 = P[8]  + P[9],  e5 = P[10] + P[11], e6 = P[12] + P[13], e7 = P[14] + P[15];
    float z2 = (e0 - e1) + (e2 - e3) + (e4 - e5) + (e6 - e7);
    float f0 = e0 + e1, f1 = e2 + e3, f2 = e4 + e5, f3 = e6 + e7;
    float z1 = (f0 - f1) + (f2 - f3);
    float z0 = (f0 + f1) - (f2 + f3);

    // Output: q_out[B,R,R,DEPTH] contiguous, reinterpreted as [B,DEPTH,R,R]
    reinterpret_cast<float4*>(out)[gid] = make_float4(z0, z1, z2, z3);
}

extern "C" void kernel_launch(void* const* d_in, const int* in_sizes, int n_in,
                              void* d_out, int out_size) {
    const float* x = (const float*)d_in[0];   // [32,3,128,128] float32
    const float* w = (const float*)d_in[1];   // [4,4] float32
    float* out = (float*)d_out;               // [32,4,127,127] float32

    prep_kernel<<<1, 16>>>(w);
    int total = NLOC;
    int blocks = (total + 255) / 256;
    rqcnn_main<<<blocks, 256>>>(x, out);
}